// round 7
// baseline (speedup 1.0000x reference)
#include <cuda_runtime.h>
#include <math.h>

#define BATCH 128
#define SEQ   1024
#define INP   7
#define HID   64
#define OUTD  500
#define MTOT  (BATCH*SEQ)   // 131072
#define FTM   128
#define FTN   128
#define HSP   20
#define NLSTM 128
#define NFC   20
#define GRID  (NLSTM + NFC)   // 148 = one wave, 1 CTA/SM
#define NJOBS (BATCH * 8)     // 1024 window jobs

typedef unsigned long long u64;

__device__ float g_hT[(size_t)HID * MTOT];   // h transposed: g_hT[k][b*SEQ+t]
__device__ volatile int g_prog[BATCH];       // lstm progress per batch
__device__ unsigned int g_ctr;               // fc job counter

// ---- f32x2 packed helpers ----
__device__ __forceinline__ u64 pack2(float a, float b) {
    u64 r;
    asm("mov.b64 %0, {%1, %2};" : "=l"(r)
        : "r"(__float_as_uint(a)), "r"(__float_as_uint(b)));
    return r;
}
__device__ __forceinline__ u64 ffma2(u64 a, u64 b, u64 c) {
    u64 d;
    asm("fma.rn.f32x2 %0, %1, %2, %3;" : "=l"(d) : "l"(a), "l"(b), "l"(c));
    return d;
}
__device__ __forceinline__ u64 fadd2(u64 a, u64 b) {
    u64 d;
    asm("add.rn.f32x2 %0, %1, %2;" : "=l"(d) : "l"(a), "l"(b));
    return d;
}
__device__ __forceinline__ void unpack2(u64 v, float& lo, float& hi) {
    unsigned int l, h;
    asm("mov.b64 {%0, %1}, %2;" : "=r"(l), "=r"(h) : "l"(v));
    lo = __uint_as_float(l); hi = __uint_as_float(h);
}
__device__ __forceinline__ float tanhf_fast(float x) {
    float y;
    asm("tanh.approx.f32 %0, %1;" : "=f"(y) : "f"(x));
    return y;
}

// ---------------------------------------------------------------------------
// FC job: one 128-step window of one batch (256 threads).
// Thread tile 8m x 8n (n strided by 16 for conflict-free LDS.64).
// B staged in smem as duplicated f32x2 pairs: zero pack overhead in k-loop.
// ---------------------------------------------------------------------------
__device__ void fc_job(char* dynsmem, int b, int w,
                       const float* __restrict__ W_fc,
                       const float* __restrict__ b_fc,
                       float* __restrict__ out)
{
    float (*As)[FTM] = (float(*)[FTM])dynsmem;                 // 32 KB
    u64   (*Bs2)[FTN] = (u64(*)[FTN])(dynsmem + HID*FTM*4);    // 64 KB

    const int tid = threadIdx.x;
    const int tx  = tid & 15;          // n lane: n = tx + 16*j
    const int ty  = tid >> 4;          // m strip: m0 = ty*8
    const int m0  = ty * 8;

    if (tid == 0) {
        while (g_prog[b] < (w + 1) * 128) { __nanosleep(200); }
        __threadfence();               // acquire
    }
    __syncthreads();

    const int rowbase = b * SEQ + w * FTM;

    // As[k][m] = g_hT[k][rowbase+m]  (coalesced, loaded once per job)
    #pragma unroll
    for (int l2 = 0; l2 < 8; ++l2) {
        int fid = tid + l2*256;
        int k   = fid >> 5;
        int m4  = (fid & 31) * 4;
        *(float4*)&As[k][m4] =
            *(const float4*)(g_hT + (size_t)k*MTOT + rowbase + m4);
    }

    for (int nt = 0; nt < 4; ++nt) {
        const int col0 = nt * FTN;
        __syncthreads();   // prior compute done / As visible on nt=0
        {   // Bs2[k][n] = (W_fc[col0+n][k], same)  — duplicated pairs
            int n  = tid >> 1;             // 0..127
            int kq = tid & 1;              // k half
            int r  = col0 + n;
            #pragma unroll
            for (int q = 0; q < 8; ++q) {
                int kf = kq*8 + q;         // float4 index: 0..15
                float4 v = make_float4(0.f,0.f,0.f,0.f);
                if (r < OUTD)
                    v = *(const float4*)(W_fc + (size_t)r*HID + kf*4);
                int kk = kf*4;
                Bs2[kk+0][n] = pack2(v.x, v.x);
                Bs2[kk+1][n] = pack2(v.y, v.y);
                Bs2[kk+2][n] = pack2(v.z, v.z);
                Bs2[kk+3][n] = pack2(v.w, v.w);
            }
        }
        __syncthreads();

        u64 acc[4][8];
        #pragma unroll
        for (int mm = 0; mm < 4; ++mm)
            #pragma unroll
            for (int j = 0; j < 8; ++j) acc[mm][j] = 0ull;

        const float* asr = &As[0][m0];
        const u64*   bsr = &Bs2[0][tx];
        #pragma unroll 4
        for (int k = 0; k < HID; ++k) {
            ulonglong2 aA = *(const ulonglong2*)(asr);
            ulonglong2 aB = *(const ulonglong2*)(asr + 4);
            u64 ap[4] = {aA.x, aA.y, aB.x, aB.y};
            u64 b2[8];
            #pragma unroll
            for (int j = 0; j < 8; ++j) b2[j] = bsr[16*j];   // LDS.64, no conflicts
            asr += FTM; bsr += FTN;
            #pragma unroll
            for (int j = 0; j < 8; ++j) {
                acc[0][j] = ffma2(ap[0], b2[j], acc[0][j]);
                acc[1][j] = ffma2(ap[1], b2[j], acc[1][j]);
                acc[2][j] = ffma2(ap[2], b2[j], acc[2][j]);
                acc[3][j] = ffma2(ap[3], b2[j], acc[3][j]);
            }
        }

        // epilogue: bias + scattered-but-coalescing STG.32
        float bias[8];
        #pragma unroll
        for (int j = 0; j < 8; ++j) {
            int n = col0 + tx + 16*j;
            bias[j] = (n < OUTD) ? b_fc[n] : 0.0f;
        }
        #pragma unroll
        for (int mm = 0; mm < 4; ++mm) {
            int r0 = rowbase + m0 + 2*mm;
            float* o0 = out + (size_t)r0 * OUTD;
            float* o1 = o0 + OUTD;
            #pragma unroll
            for (int j = 0; j < 8; ++j) {
                int n = col0 + tx + 16*j;
                if (n < OUTD) {
                    float lo, hi; unpack2(acc[mm][j], lo, hi);
                    o0[n] = lo + bias[j];
                    o1[n] = hi + bias[j];
                }
            }
        }
    }
    __syncthreads();
}

// work-stealing drain of fc jobs (CTA-uniform via smem broadcast)
__device__ void steal_loop(char* dynsmem, int* jobS,
                           const float* __restrict__ W_fc,
                           const float* __restrict__ b_fc,
                           float* __restrict__ out)
{
    const int tid = threadIdx.x;
    for (;;) {
        if (tid == 0) *jobS = (int)atomicAdd(&g_ctr, 1u);
        __syncthreads();
        int j = *jobS;
        __syncthreads();
        if (j >= NJOBS) break;
        // w-major: early jobs are the earliest-available windows
        fc_job(dynsmem, j & (BATCH-1), j >> 7, W_fc, b_fc, out);
    }
}

// ---------------------------------------------------------------------------
// Fused kernel: blocks 0..127 = lstm (round-3 core, 1 batch/CTA), then join
// stealing. Blocks 128..147 = dedicated fc consumers from the start.
// One wave, 1 CTA/SM -> zero SM sharing with the recurrence.
// ---------------------------------------------------------------------------
__global__ __launch_bounds__(256, 1)
void fused_kernel(const float* __restrict__ x,
                  const float* __restrict__ W_ih,
                  const float* __restrict__ W_hh,
                  const float* __restrict__ b_ih,
                  const float* __restrict__ b_hh,
                  const float* __restrict__ W_fc,
                  const float* __restrict__ b_fc,
                  float* __restrict__ out)
{
    extern __shared__ char dynsmem[];
    __shared__ int jobS;
    const int bid = blockIdx.x;
    const int tid = threadIdx.x;

    if (bid >= NLSTM) {
        steal_loop(dynsmem, &jobS, W_fc, b_fc, out);
        return;
    }

    // ---------------- LSTM role (round-3 core) ----------------
    float* xs     = (float*)dynsmem;                 // 28672 B
    float* hb     = xs + SEQ*INP;                    // [2][HID] 512 B
    float* hstage = hb + 2*HID;                      // [2][HID][HSP] 10240 B

    const int b    = bid;
    const int hh   = tid >> 2;
    const int gate = tid & 3;
    const int row  = gate * HID + hh;
    const int lane = tid & 31;
    const int lb   = lane & ~3;

    {
        const float4* src = (const float4*)(x + (size_t)b * SEQ * INP);
        float4* dst = (float4*)xs;
        #pragma unroll
        for (int i = 0; i < (SEQ*INP)/(4*256); ++i)
            dst[tid + i*256] = src[tid + i*256];
    }

    u64 w2[HID/2];
    {
        const ulonglong2* wr = (const ulonglong2*)(W_hh + (size_t)row * HID);
        #pragma unroll
        for (int i = 0; i < HID/4; ++i) {
            ulonglong2 v = wr[i];
            w2[2*i+0] = v.x; w2[2*i+1] = v.y;
        }
    }
    float wih[INP];
    #pragma unroll
    for (int i = 0; i < INP; ++i) wih[i] = W_ih[row*INP + i];
    const float bias = b_ih[row] + b_hh[row];

    const float scale = (gate == 2) ? 1.0f : 0.5f;
    const float off   = (gate == 2) ? 0.0f : 0.5f;

    if (tid < HID) hb[tid] = 0.0f;
    float c = 0.0f;
    __syncthreads();

    float xacc = bias;
    #pragma unroll
    for (int i = 0; i < INP; ++i) xacc = fmaf(xs[i], wih[i], xacc);

    int cur = 0;
    for (int t = 0; t < SEQ; ++t) {
        const ulonglong2* hv = (const ulonglong2*)(hb + cur*HID);
        u64 a[8];
        #pragma unroll
        for (int i = 0; i < 8; ++i) a[i] = 0ull;
        #pragma unroll
        for (int j = 0; j < 4; ++j) {
            ulonglong2 h0 = hv[4*j+0];
            ulonglong2 h1 = hv[4*j+1];
            ulonglong2 h2 = hv[4*j+2];
            ulonglong2 h3 = hv[4*j+3];
            a[0] = ffma2(h0.x, w2[8*j+0], a[0]);
            a[1] = ffma2(h0.y, w2[8*j+1], a[1]);
            a[2] = ffma2(h1.x, w2[8*j+2], a[2]);
            a[3] = ffma2(h1.y, w2[8*j+3], a[3]);
            a[4] = ffma2(h2.x, w2[8*j+4], a[4]);
            a[5] = ffma2(h2.y, w2[8*j+5], a[5]);
            a[6] = ffma2(h3.x, w2[8*j+6], a[6]);
            a[7] = ffma2(h3.y, w2[8*j+7], a[7]);
        }
        u64 s0 = fadd2(a[0], a[1]);
        u64 s1 = fadd2(a[2], a[3]);
        u64 s2 = fadd2(a[4], a[5]);
        u64 s3 = fadd2(a[6], a[7]);
        u64 s  = fadd2(fadd2(s0, s1), fadd2(s2, s3));
        float slo, shi; unpack2(s, slo, shi);
        float pre = xacc + slo + shi;

        float act = fmaf(scale, tanhf_fast(scale * pre), off);

        float ig = __shfl_sync(0xffffffffu, act, lb+0);
        float fg = __shfl_sync(0xffffffffu, act, lb+1);
        float gg = __shfl_sync(0xffffffffu, act, lb+2);
        float og = __shfl_sync(0xffffffffu, act, lb+3);

        c = fmaf(fg, c, ig*gg);
        float h = og * tanhf_fast(c);
        if (gate == 0) {
            hb[(cur^1)*HID + hh] = h;
            hstage[(((t>>4)&1)*HID + hh)*HSP + (t & 15)] = h;
        }

        int tn = (t + 1 < SEQ) ? t + 1 : 0;
        const float* xt = xs + tn*INP;
        float xn = bias;
        #pragma unroll
        for (int i = 0; i < INP; ++i) xn = fmaf(xt[i], wih[i], xn);
        xacc = xn;

        __syncthreads();
        cur ^= 1;

        if ((t & 15) == 15) {
            int wsel = (t >> 4) & 1;
            int k = tid >> 2;
            int j = (tid & 3) * 4;
            const float* hp = &hstage[(wsel*HID + k)*HSP + j];
            float4 v = make_float4(hp[0], hp[1], hp[2], hp[3]);
            *(float4*)(g_hT + (size_t)k*MTOT + (size_t)b*SEQ + (t-15) + j) = v;
            __threadfence();
        } else if ((t & 15) == 0 && t != 0) {
            if (tid == 0) g_prog[b] = t;
        }
    }

    __syncthreads();
    if (tid == 0) g_prog[b] = SEQ;
    __syncthreads();

    // recurrence done: join the fc drain
    steal_loop(dynsmem, &jobS, W_fc, b_fc, out);
}

// reset counter + flags each launch (graph-captured as first node)
__global__ void reset_kernel()
{
    int i = threadIdx.x;
    if (i == 0) g_ctr = 0;
    if (i < BATCH) g_prog[i] = 0;
}

extern "C" void kernel_launch(void* const* d_in, const int* in_sizes, int n_in,
                              void* d_out, int out_size)
{
    const float* x    = (const float*)d_in[0];
    const float* W_ih = (const float*)d_in[1];
    const float* W_hh = (const float*)d_in[2];
    const float* b_ih = (const float*)d_in[3];
    const float* b_hh = (const float*)d_in[4];
    const float* W_fc = (const float*)d_in[5];
    const float* b_fc = (const float*)d_in[6];
    float* out = (float*)d_out;

    static int smem_set = 0;
    const int dyn = 96 * 1024;       // fc: 32K As + 64K Bs2 ; lstm: ~39K
    if (!smem_set) {
        cudaFuncSetAttribute(fused_kernel,
                             cudaFuncAttributeMaxDynamicSharedMemorySize, dyn);
        smem_set = 1;
    }
    reset_kernel<<<1, 128>>>();
    fused_kernel<<<GRID, 256, dyn>>>(x, W_ih, W_hh, b_ih, b_hh, W_fc, b_fc, out);
}